// round 10
// baseline (speedup 1.0000x reference)
#include <cuda_runtime.h>
#include <cstdint>

// ResidualGraphConv via Horner over combined channels Wc[d] = [W1[d]; W2[d]]:
//   V = U3;  V = V*A + U2;  V = V*A + U1;  out = V*A + U0 (+bias, relu upper 32)
// with U_d = Wc[d] @ x fused as two trailing K=32 chunks of each GEMM.
//
// GEMM per step per batch: C[64,2048] = V[64,2048] * A[2048,2048].
// mma.sync.m16n8k8 tf32 (RNA rounding at fragment load), cp.async 3-stage
// pipeline, NT=64 column tiles -> grid 512, 4 CTAs/SM, single wave.

#define BATCH 16
#define CCH   64
#define NN    2048
#define NT    64
#define KB    32
#define LDA   36                    // As rows: 32 data + 4 pad floats (16B pad)
#define LDB   72                    // Bs rows: 64 data + 8 pad floats (32B pad)
#define A_FLOATS   (CCH * LDA)      // 2304
#define STAGE_FLOATS (A_FLOATS + KB * LDB)  // 4608 floats = 18432 B
#define STAGES 3
#define SMEM_BYTES (STAGES * STAGE_FLOATS * 4)  // 55296

__device__ float g_V0[BATCH * CCH * NN];
__device__ float g_V1[BATCH * CCH * NN];

__device__ __forceinline__ uint32_t ftf32(float v) {
    uint32_t u;
    asm("cvt.rna.tf32.f32 %0, %1;" : "=r"(u) : "f"(v));
    return u;
}

__device__ __forceinline__ void cp_async16(uint32_t smem_addr, const float* gptr) {
    asm volatile("cp.async.cg.shared.global [%0], [%1], 16;\n"
                 :: "r"(smem_addr), "l"(gptr));
}
__device__ __forceinline__ void cp_commit() {
    asm volatile("cp.async.commit_group;\n" ::: "memory");
}
__device__ __forceinline__ void cp_wait1() {
    asm volatile("cp.async.wait_group 1;\n" ::: "memory");
}

__device__ __forceinline__ void mma_tf32(float* c,
                                         uint32_t a0, uint32_t a1, uint32_t a2, uint32_t a3,
                                         uint32_t b0, uint32_t b1) {
    asm volatile(
        "mma.sync.aligned.m16n8k8.row.col.f32.tf32.tf32.f32 "
        "{%0,%1,%2,%3}, {%4,%5,%6,%7}, {%8,%9}, {%0,%1,%2,%3};\n"
        : "+f"(c[0]), "+f"(c[1]), "+f"(c[2]), "+f"(c[3])
        : "r"(a0), "r"(a1), "r"(a2), "r"(a3), "r"(b0), "r"(b1));
}

// vin_sel: 0 -> g_V0, 1 -> g_V1. vout_sel: 0 -> g_V0, 1 -> g_V1, 2 -> dout (+bias/relu)
__global__ void __launch_bounds__(256, 4)
horner_kernel(const float* __restrict__ adj,
              const float* __restrict__ x,
              const float* __restrict__ W1,
              const float* __restrict__ W2,
              const float* __restrict__ bias1,
              const float* __restrict__ bias2,
              float* __restrict__ dout,
              int nk_main, int deg, int vin_sel, int vout_sel) {
    extern __shared__ float sm[];

    const int tid  = threadIdx.x;
    const int lane = tid & 31;
    const int wid  = tid >> 5;
    const int wm   = wid & 3;          // warp row (16 channels)
    const int wn   = wid >> 2;         // warp col (32 cols)
    const int g    = lane >> 2;
    const int t    = lane & 3;
    const int b    = blockIdx.y;
    const int m0   = blockIdx.x * NT;

    const float* Vin  = vin_sel ? g_V1 : g_V0;
    float*       Vout = (vout_sel == 0) ? g_V0 : ((vout_sel == 1) ? g_V1 : dout);

    const int nchunks = nk_main + 2;

    // ---- per-thread cp.async staging coordinates ----
    const int arow = tid >> 3;          // A rows: arow, arow+32  (0..63)
    const int aq   = tid & 7;           // float4 within 32-float k-row
    const int brow = tid >> 4;          // B k-rows: brow, brow+16 (0..31)
    const int bq   = tid & 15;          // float4 within 64-float m-row

    const uint32_t smbase = (uint32_t)__cvta_generic_to_shared(sm);

    auto load_chunk = [&](int cc, int stage) {
        if (cc >= nchunks) { cp_commit(); return; }
        const bool isU = (cc >= nk_main);
        const int  k0  = cc * KB;
        const int  ci0 = (cc - nk_main) * KB;
        const uint32_t sA = smbase + (uint32_t)(stage * STAGE_FLOATS) * 4u;
        const uint32_t sB = sA + A_FLOATS * 4u;
#pragma unroll
        for (int i = 0; i < 2; i++) {
            const int r = arow + 32 * i;
            const float* src;
            if (!isU) {
                src = Vin + ((b << 6) + r) * NN + k0 + (aq << 2);
            } else {
                const float* W = (r < 32) ? W1 : W2;
                src = W + ((deg * 32 + (r & 31)) << 6) + ci0 + (aq << 2);
            }
            cp_async16(sA + (uint32_t)(r * LDA + (aq << 2)) * 4u, src);
        }
#pragma unroll
        for (int i = 0; i < 2; i++) {
            const int k = brow + 16 * i;
            const float* src;
            if (!isU) {
                src = adj + (size_t)(b * NN + k0 + k) * NN + m0 + (bq << 2);
            } else {
                src = x + ((b << 6) + ci0 + k) * NN + m0 + (bq << 2);
            }
            cp_async16(sB + (uint32_t)(k * LDB + (bq << 2)) * 4u, src);
        }
        cp_commit();
    };

    float acc[4][4];
#pragma unroll
    for (int j = 0; j < 4; j++)
#pragma unroll
        for (int i = 0; i < 4; i++) acc[j][i] = 0.0f;

    // fragment index bases (in floats)
    const int r0    = wm * 16 + g;
    const int aoff  = r0 * LDA + t;            // + kb, +4, +8*LDA
    const int boff  = t * LDB + wn * 32 + g;   // + kb*LDB, +4*LDB, + j*8

    // ---- prologue: stages 0..STAGES-2 ----
    load_chunk(0, 0);
    load_chunk(1, 1);

    for (int cc = 0; cc < nchunks; cc++) {
        cp_wait1();            // stage cc landed
        __syncthreads();       // visible to all; also: everyone done reading stage cc-1

        // issue loads for chunk cc+2 into buffer (cc+2)%3 == (cc-1)%3 (freed above)
        load_chunk(cc + 2, (cc + 2) % STAGES);

        const float* As = sm + (cc % STAGES) * STAGE_FLOATS;
        const float* Bs = As + A_FLOATS;

#pragma unroll
        for (int kk = 0; kk < 4; kk++) {
            const int kb = kk * 8;
            uint32_t a0 = ftf32(As[aoff + kb]);
            uint32_t a1 = ftf32(As[aoff + 8 * LDA + kb]);
            uint32_t a2 = ftf32(As[aoff + kb + 4]);
            uint32_t a3 = ftf32(As[aoff + 8 * LDA + kb + 4]);
#pragma unroll
            for (int j = 0; j < 4; j++) {
                uint32_t b0 = ftf32(Bs[boff + kb * LDB + j * 8]);
                uint32_t b1 = ftf32(Bs[boff + (kb + 4) * LDB + j * 8]);
                mma_tf32(acc[j], a0, a1, a2, a3, b0, b1);
            }
        }
    }

    // ---- epilogue ----
    const int r1 = r0 + 8;
    float add0 = 0.0f, add1 = 0.0f;
    bool relu0 = false, relu1 = false;
    if (vout_sel == 2) {
        add0 = (r0 < 32) ? bias1[r0] : bias2[r0 - 32];
        add1 = (r1 < 32) ? bias1[r1] : bias2[r1 - 32];
        relu0 = (r0 >= 32);
        relu1 = (r1 >= 32);
    }
#pragma unroll
    for (int j = 0; j < 4; j++) {
        const int m = m0 + wn * 32 + j * 8 + 2 * t;
        float v0 = acc[j][0], v1 = acc[j][1];   // row r0
        float v2 = acc[j][2], v3 = acc[j][3];   // row r1
        if (vout_sel == 2) {
            v0 += add0; v1 += add0;
            v2 += add1; v3 += add1;
            if (relu0) { v0 = fmaxf(v0, 0.0f); v1 = fmaxf(v1, 0.0f); }
            if (relu1) { v2 = fmaxf(v2, 0.0f); v3 = fmaxf(v3, 0.0f); }
        }
        *reinterpret_cast<float2*>(&Vout[((b << 6) + r0) * NN + m]) = make_float2(v0, v1);
        *reinterpret_cast<float2*>(&Vout[((b << 6) + r1) * NN + m]) = make_float2(v2, v3);
    }
}

extern "C" void kernel_launch(void* const* d_in, const int* in_sizes, int n_in,
                              void* d_out, int out_size) {
    (void)in_sizes; (void)n_in; (void)out_size;
    const float* adj = (const float*)d_in[0];   // [16,2048,2048]
    const float* x   = (const float*)d_in[1];   // [16,64,2048]
    const float* W1  = (const float*)d_in[2];   // [4,32,64]
    const float* b1  = (const float*)d_in[3];   // [32]
    const float* W2  = (const float*)d_in[4];   // [4,32,64]
    const float* b2  = (const float*)d_in[5];   // [32]
    float* out = (float*)d_out;                 // [16,64,2048]

    cudaFuncSetAttribute(horner_kernel,
                         cudaFuncAttributeMaxDynamicSharedMemorySize, SMEM_BYTES);

    dim3 grid(NN / NT, BATCH);   // 32 x 16 = 512 CTAs -> single wave @ 4 CTA/SM
    dim3 block(256);

    // V0 = U3
    horner_kernel<<<grid, block, SMEM_BYTES>>>(adj, x, W1, W2, b1, b2, out, 0, 3, 0, 0);
    // V1 = V0*A + U2
    horner_kernel<<<grid, block, SMEM_BYTES>>>(adj, x, W1, W2, b1, b2, out, NN / KB, 2, 0, 1);
    // V0 = V1*A + U1
    horner_kernel<<<grid, block, SMEM_BYTES>>>(adj, x, W1, W2, b1, b2, out, NN / KB, 1, 1, 0);
    // out = V0*A + U0 + bias, relu upper half
    horner_kernel<<<grid, block, SMEM_BYTES>>>(adj, x, W1, W2, b1, b2, out, NN / KB, 0, 0, 2);
}

// round 11
// speedup vs baseline: 1.0049x; 1.0049x over previous
#include <cuda_runtime.h>
#include <cstdint>

// ResidualGraphConv via Horner over combined channels Wc[d] = [W1[d]; W2[d]]:
//   V = U3;  V = V*A + U2;  V = V*A + U1;  out = V*A + U0 (+bias, relu upper 32)
// with U_d = Wc[d] @ x fused as two trailing K=32 chunks of each GEMM.
//
// GEMM per step per batch: C[64,2048] = V[64,2048] * A[2048,2048].
// mma.sync.m16n8k8 tf32 (RNA rounding at fragment load), cp.async 3-stage
// pipeline, NT=64 column tiles -> grid 512, 4 CTAs/SM, single wave.

#define BATCH 16
#define CCH   64
#define NN    2048
#define NT    64
#define KB    32
#define LDA   36                    // As rows: 32 data + 4 pad floats (16B pad)
#define LDB   72                    // Bs rows: 64 data + 8 pad floats (32B pad)
#define A_FLOATS   (CCH * LDA)      // 2304
#define STAGE_FLOATS (A_FLOATS + KB * LDB)  // 4608 floats = 18432 B
#define STAGES 3
#define SMEM_BYTES (STAGES * STAGE_FLOATS * 4)  // 55296

__device__ float g_V0[BATCH * CCH * NN];
__device__ float g_V1[BATCH * CCH * NN];

__device__ __forceinline__ uint32_t ftf32(float v) {
    uint32_t u;
    asm("cvt.rna.tf32.f32 %0, %1;" : "=r"(u) : "f"(v));
    return u;
}

__device__ __forceinline__ void cp_async16(uint32_t smem_addr, const float* gptr) {
    asm volatile("cp.async.cg.shared.global [%0], [%1], 16;\n"
                 :: "r"(smem_addr), "l"(gptr));
}
__device__ __forceinline__ void cp_commit() {
    asm volatile("cp.async.commit_group;\n" ::: "memory");
}
__device__ __forceinline__ void cp_wait1() {
    asm volatile("cp.async.wait_group 1;\n" ::: "memory");
}

__device__ __forceinline__ void mma_tf32(float* c,
                                         uint32_t a0, uint32_t a1, uint32_t a2, uint32_t a3,
                                         uint32_t b0, uint32_t b1) {
    asm volatile(
        "mma.sync.aligned.m16n8k8.row.col.f32.tf32.tf32.f32 "
        "{%0,%1,%2,%3}, {%4,%5,%6,%7}, {%8,%9}, {%0,%1,%2,%3};\n"
        : "+f"(c[0]), "+f"(c[1]), "+f"(c[2]), "+f"(c[3])
        : "r"(a0), "r"(a1), "r"(a2), "r"(a3), "r"(b0), "r"(b1));
}

// vin_sel: 0 -> g_V0, 1 -> g_V1. vout_sel: 0 -> g_V0, 1 -> g_V1, 2 -> dout (+bias/relu)
__global__ void __launch_bounds__(256, 4)
horner_kernel(const float* __restrict__ adj,
              const float* __restrict__ x,
              const float* __restrict__ W1,
              const float* __restrict__ W2,
              const float* __restrict__ bias1,
              const float* __restrict__ bias2,
              float* __restrict__ dout,
              int nk_main, int deg, int vin_sel, int vout_sel) {
    extern __shared__ float sm[];

    const int tid  = threadIdx.x;
    const int lane = tid & 31;
    const int wid  = tid >> 5;
    const int wm   = wid & 3;          // warp row (16 channels)
    const int wn   = wid >> 2;         // warp col (32 cols)
    const int g    = lane >> 2;
    const int t    = lane & 3;
    const int b    = blockIdx.y;
    const int m0   = blockIdx.x * NT;

    const float* Vin  = vin_sel ? g_V1 : g_V0;
    float*       Vout = (vout_sel == 0) ? g_V0 : ((vout_sel == 1) ? g_V1 : dout);

    const int nchunks = nk_main + 2;

    // ---- per-thread cp.async staging coordinates ----
    const int arow = tid >> 3;          // A rows: arow, arow+32  (0..63)
    const int aq   = tid & 7;           // float4 within 32-float k-row
    const int brow = tid >> 4;          // B k-rows: brow, brow+16 (0..31)
    const int bq   = tid & 15;          // float4 within 64-float m-row

    const uint32_t smbase = (uint32_t)__cvta_generic_to_shared(sm);

    auto load_chunk = [&](int cc, int stage) {
        if (cc >= nchunks) { cp_commit(); return; }
        const bool isU = (cc >= nk_main);
        const int  k0  = cc * KB;
        const int  ci0 = (cc - nk_main) * KB;
        const uint32_t sA = smbase + (uint32_t)(stage * STAGE_FLOATS) * 4u;
        const uint32_t sB = sA + A_FLOATS * 4u;
#pragma unroll
        for (int i = 0; i < 2; i++) {
            const int r = arow + 32 * i;
            const float* src;
            if (!isU) {
                src = Vin + ((b << 6) + r) * NN + k0 + (aq << 2);
            } else {
                const float* W = (r < 32) ? W1 : W2;
                src = W + ((deg * 32 + (r & 31)) << 6) + ci0 + (aq << 2);
            }
            cp_async16(sA + (uint32_t)(r * LDA + (aq << 2)) * 4u, src);
        }
#pragma unroll
        for (int i = 0; i < 2; i++) {
            const int k = brow + 16 * i;
            const float* src;
            if (!isU) {
                src = adj + (size_t)(b * NN + k0 + k) * NN + m0 + (bq << 2);
            } else {
                src = x + ((b << 6) + ci0 + k) * NN + m0 + (bq << 2);
            }
            cp_async16(sB + (uint32_t)(k * LDB + (bq << 2)) * 4u, src);
        }
        cp_commit();
    };

    float acc[4][4];
#pragma unroll
    for (int j = 0; j < 4; j++)
#pragma unroll
        for (int i = 0; i < 4; i++) acc[j][i] = 0.0f;

    // fragment index bases (in floats)
    const int r0    = wm * 16 + g;
    const int aoff  = r0 * LDA + t;            // + kb, +4, +8*LDA
    const int boff  = t * LDB + wn * 32 + g;   // + kb*LDB, +4*LDB, + j*8

    // ---- prologue: stages 0..STAGES-2 ----
    load_chunk(0, 0);
    load_chunk(1, 1);

    for (int cc = 0; cc < nchunks; cc++) {
        cp_wait1();            // stage cc landed
        __syncthreads();       // visible to all; also: everyone done reading stage cc-1

        // issue loads for chunk cc+2 into buffer (cc+2)%3 == (cc-1)%3 (freed above)
        load_chunk(cc + 2, (cc + 2) % STAGES);

        const float* As = sm + (cc % STAGES) * STAGE_FLOATS;
        const float* Bs = As + A_FLOATS;

#pragma unroll
        for (int kk = 0; kk < 4; kk++) {
            const int kb = kk * 8;
            uint32_t a0 = ftf32(As[aoff + kb]);
            uint32_t a1 = ftf32(As[aoff + 8 * LDA + kb]);
            uint32_t a2 = ftf32(As[aoff + kb + 4]);
            uint32_t a3 = ftf32(As[aoff + 8 * LDA + kb + 4]);
#pragma unroll
            for (int j = 0; j < 4; j++) {
                uint32_t b0 = ftf32(Bs[boff + kb * LDB + j * 8]);
                uint32_t b1 = ftf32(Bs[boff + (kb + 4) * LDB + j * 8]);
                mma_tf32(acc[j], a0, a1, a2, a3, b0, b1);
            }
        }
    }

    // ---- epilogue ----
    const int r1 = r0 + 8;
    float add0 = 0.0f, add1 = 0.0f;
    bool relu0 = false, relu1 = false;
    if (vout_sel == 2) {
        add0 = (r0 < 32) ? bias1[r0] : bias2[r0 - 32];
        add1 = (r1 < 32) ? bias1[r1] : bias2[r1 - 32];
        relu0 = (r0 >= 32);
        relu1 = (r1 >= 32);
    }
#pragma unroll
    for (int j = 0; j < 4; j++) {
        const int m = m0 + wn * 32 + j * 8 + 2 * t;
        float v0 = acc[j][0], v1 = acc[j][1];   // row r0
        float v2 = acc[j][2], v3 = acc[j][3];   // row r1
        if (vout_sel == 2) {
            v0 += add0; v1 += add0;
            v2 += add1; v3 += add1;
            if (relu0) { v0 = fmaxf(v0, 0.0f); v1 = fmaxf(v1, 0.0f); }
            if (relu1) { v2 = fmaxf(v2, 0.0f); v3 = fmaxf(v3, 0.0f); }
        }
        *reinterpret_cast<float2*>(&Vout[((b << 6) + r0) * NN + m]) = make_float2(v0, v1);
        *reinterpret_cast<float2*>(&Vout[((b << 6) + r1) * NN + m]) = make_float2(v2, v3);
    }
}

extern "C" void kernel_launch(void* const* d_in, const int* in_sizes, int n_in,
                              void* d_out, int out_size) {
    (void)in_sizes; (void)n_in; (void)out_size;
    const float* adj = (const float*)d_in[0];   // [16,2048,2048]
    const float* x   = (const float*)d_in[1];   // [16,64,2048]
    const float* W1  = (const float*)d_in[2];   // [4,32,64]
    const float* b1  = (const float*)d_in[3];   // [32]
    const float* W2  = (const float*)d_in[4];   // [4,32,64]
    const float* b2  = (const float*)d_in[5];   // [32]
    float* out = (float*)d_out;                 // [16,64,2048]

    cudaFuncSetAttribute(horner_kernel,
                         cudaFuncAttributeMaxDynamicSharedMemorySize, SMEM_BYTES);

    dim3 grid(NN / NT, BATCH);   // 32 x 16 = 512 CTAs -> single wave @ 4 CTA/SM
    dim3 block(256);

    // V0 = U3
    horner_kernel<<<grid, block, SMEM_BYTES>>>(adj, x, W1, W2, b1, b2, out, 0, 3, 0, 0);
    // V1 = V0*A + U2
    horner_kernel<<<grid, block, SMEM_BYTES>>>(adj, x, W1, W2, b1, b2, out, NN / KB, 2, 0, 1);
    // V0 = V1*A + U1
    horner_kernel<<<grid, block, SMEM_BYTES>>>(adj, x, W1, W2, b1, b2, out, NN / KB, 1, 1, 0);
    // out = V0*A + U0 + bias, relu upper half
    horner_kernel<<<grid, block, SMEM_BYTES>>>(adj, x, W1, W2, b1, b2, out, NN / KB, 0, 0, 2);
}

// round 12
// speedup vs baseline: 1.0053x; 1.0004x over previous
#include <cuda_runtime.h>
#include <cstdint>

// ResidualGraphConv via Horner over combined channels Wc[d] = [W1[d]; W2[d]]:
//   V = U3;  V = V*A + U2;  V = V*A + U1;  out = V*A + U0 (+bias, relu upper 32)
// with U_d = Wc[d] @ x fused as two trailing K=32 chunks of each GEMM.
//
// GEMM per step per batch: C[64,2048] = V[64,2048] * A[2048,2048].
// mma.sync.m16n8k8 tf32 (RNA rounding at fragment load), cp.async 3-stage
// pipeline, NT=64 column tiles -> grid 512, 4 CTAs/SM, single wave.

#define BATCH 16
#define CCH   64
#define NN    2048
#define NT    64
#define KB    32
#define LDA   36                    // As rows: 32 data + 4 pad floats (16B pad)
#define LDB   72                    // Bs rows: 64 data + 8 pad floats (32B pad)
#define A_FLOATS   (CCH * LDA)      // 2304
#define STAGE_FLOATS (A_FLOATS + KB * LDB)  // 4608 floats = 18432 B
#define STAGES 3
#define SMEM_BYTES (STAGES * STAGE_FLOATS * 4)  // 55296

__device__ float g_V0[BATCH * CCH * NN];
__device__ float g_V1[BATCH * CCH * NN];

__device__ __forceinline__ uint32_t ftf32(float v) {
    uint32_t u;
    asm("cvt.rna.tf32.f32 %0, %1;" : "=r"(u) : "f"(v));
    return u;
}

__device__ __forceinline__ void cp_async16(uint32_t smem_addr, const float* gptr) {
    asm volatile("cp.async.cg.shared.global [%0], [%1], 16;\n"
                 :: "r"(smem_addr), "l"(gptr));
}
__device__ __forceinline__ void cp_commit() {
    asm volatile("cp.async.commit_group;\n" ::: "memory");
}
__device__ __forceinline__ void cp_wait1() {
    asm volatile("cp.async.wait_group 1;\n" ::: "memory");
}

__device__ __forceinline__ void mma_tf32(float* c,
                                         uint32_t a0, uint32_t a1, uint32_t a2, uint32_t a3,
                                         uint32_t b0, uint32_t b1) {
    asm volatile(
        "mma.sync.aligned.m16n8k8.row.col.f32.tf32.tf32.f32 "
        "{%0,%1,%2,%3}, {%4,%5,%6,%7}, {%8,%9}, {%0,%1,%2,%3};\n"
        : "+f"(c[0]), "+f"(c[1]), "+f"(c[2]), "+f"(c[3])
        : "r"(a0), "r"(a1), "r"(a2), "r"(a3), "r"(b0), "r"(b1));
}

// vin_sel: 0 -> g_V0, 1 -> g_V1. vout_sel: 0 -> g_V0, 1 -> g_V1, 2 -> dout (+bias/relu)
__global__ void __launch_bounds__(256, 4)
horner_kernel(const float* __restrict__ adj,
              const float* __restrict__ x,
              const float* __restrict__ W1,
              const float* __restrict__ W2,
              const float* __restrict__ bias1,
              const float* __restrict__ bias2,
              float* __restrict__ dout,
              int nk_main, int deg, int vin_sel, int vout_sel) {
    extern __shared__ float sm[];

    const int tid  = threadIdx.x;
    const int lane = tid & 31;
    const int wid  = tid >> 5;
    const int wm   = wid & 3;          // warp row (16 channels)
    const int wn   = wid >> 2;         // warp col (32 cols)
    const int g    = lane >> 2;
    const int t    = lane & 3;
    const int b    = blockIdx.y;
    const int m0   = blockIdx.x * NT;

    const float* Vin  = vin_sel ? g_V1 : g_V0;
    float*       Vout = (vout_sel == 0) ? g_V0 : ((vout_sel == 1) ? g_V1 : dout);

    const int nchunks = nk_main + 2;

    // ---- per-thread cp.async staging coordinates ----
    const int arow = tid >> 3;          // A rows: arow, arow+32  (0..63)
    const int aq   = tid & 7;           // float4 within 32-float k-row
    const int brow = tid >> 4;          // B k-rows: brow, brow+16 (0..31)
    const int bq   = tid & 15;          // float4 within 64-float m-row

    const uint32_t smbase = (uint32_t)__cvta_generic_to_shared(sm);

    auto load_chunk = [&](int cc, int stage) {
        if (cc >= nchunks) { cp_commit(); return; }
        const bool isU = (cc >= nk_main);
        const int  k0  = cc * KB;
        const int  ci0 = (cc - nk_main) * KB;
        const uint32_t sA = smbase + (uint32_t)(stage * STAGE_FLOATS) * 4u;
        const uint32_t sB = sA + A_FLOATS * 4u;
#pragma unroll
        for (int i = 0; i < 2; i++) {
            const int r = arow + 32 * i;
            const float* src;
            if (!isU) {
                src = Vin + ((b << 6) + r) * NN + k0 + (aq << 2);
            } else {
                const float* W = (r < 32) ? W1 : W2;
                src = W + ((deg * 32 + (r & 31)) << 6) + ci0 + (aq << 2);
            }
            cp_async16(sA + (uint32_t)(r * LDA + (aq << 2)) * 4u, src);
        }
#pragma unroll
        for (int i = 0; i < 2; i++) {
            const int k = brow + 16 * i;
            const float* src;
            if (!isU) {
                src = adj + (size_t)(b * NN + k0 + k) * NN + m0 + (bq << 2);
            } else {
                src = x + ((b << 6) + ci0 + k) * NN + m0 + (bq << 2);
            }
            cp_async16(sB + (uint32_t)(k * LDB + (bq << 2)) * 4u, src);
        }
        cp_commit();
    };

    float acc[4][4];
#pragma unroll
    for (int j = 0; j < 4; j++)
#pragma unroll
        for (int i = 0; i < 4; i++) acc[j][i] = 0.0f;

    // fragment index bases (in floats)
    const int r0    = wm * 16 + g;
    const int aoff  = r0 * LDA + t;            // + kb, +4, +8*LDA
    const int boff  = t * LDB + wn * 32 + g;   // + kb*LDB, +4*LDB, + j*8

    // ---- prologue: stages 0..STAGES-2 ----
    load_chunk(0, 0);
    load_chunk(1, 1);

    for (int cc = 0; cc < nchunks; cc++) {
        cp_wait1();            // stage cc landed
        __syncthreads();       // visible to all; also: everyone done reading stage cc-1

        // issue loads for chunk cc+2 into buffer (cc+2)%3 == (cc-1)%3 (freed above)
        load_chunk(cc + 2, (cc + 2) % STAGES);

        const float* As = sm + (cc % STAGES) * STAGE_FLOATS;
        const float* Bs = As + A_FLOATS;

#pragma unroll
        for (int kk = 0; kk < 4; kk++) {
            const int kb = kk * 8;
            uint32_t a0 = ftf32(As[aoff + kb]);
            uint32_t a1 = ftf32(As[aoff + 8 * LDA + kb]);
            uint32_t a2 = ftf32(As[aoff + kb + 4]);
            uint32_t a3 = ftf32(As[aoff + 8 * LDA + kb + 4]);
#pragma unroll
            for (int j = 0; j < 4; j++) {
                uint32_t b0 = ftf32(Bs[boff + kb * LDB + j * 8]);
                uint32_t b1 = ftf32(Bs[boff + (kb + 4) * LDB + j * 8]);
                mma_tf32(acc[j], a0, a1, a2, a3, b0, b1);
            }
        }
    }

    // ---- epilogue ----
    const int r1 = r0 + 8;
    float add0 = 0.0f, add1 = 0.0f;
    bool relu0 = false, relu1 = false;
    if (vout_sel == 2) {
        add0 = (r0 < 32) ? bias1[r0] : bias2[r0 - 32];
        add1 = (r1 < 32) ? bias1[r1] : bias2[r1 - 32];
        relu0 = (r0 >= 32);
        relu1 = (r1 >= 32);
    }
#pragma unroll
    for (int j = 0; j < 4; j++) {
        const int m = m0 + wn * 32 + j * 8 + 2 * t;
        float v0 = acc[j][0], v1 = acc[j][1];   // row r0
        float v2 = acc[j][2], v3 = acc[j][3];   // row r1
        if (vout_sel == 2) {
            v0 += add0; v1 += add0;
            v2 += add1; v3 += add1;
            if (relu0) { v0 = fmaxf(v0, 0.0f); v1 = fmaxf(v1, 0.0f); }
            if (relu1) { v2 = fmaxf(v2, 0.0f); v3 = fmaxf(v3, 0.0f); }
        }
        *reinterpret_cast<float2*>(&Vout[((b << 6) + r0) * NN + m]) = make_float2(v0, v1);
        *reinterpret_cast<float2*>(&Vout[((b << 6) + r1) * NN + m]) = make_float2(v2, v3);
    }
}

extern "C" void kernel_launch(void* const* d_in, const int* in_sizes, int n_in,
                              void* d_out, int out_size) {
    (void)in_sizes; (void)n_in; (void)out_size;
    const float* adj = (const float*)d_in[0];   // [16,2048,2048]
    const float* x   = (const float*)d_in[1];   // [16,64,2048]
    const float* W1  = (const float*)d_in[2];   // [4,32,64]
    const float* b1  = (const float*)d_in[3];   // [32]
    const float* W2  = (const float*)d_in[4];   // [4,32,64]
    const float* b2  = (const float*)d_in[5];   // [32]
    float* out = (float*)d_out;                 // [16,64,2048]

    cudaFuncSetAttribute(horner_kernel,
                         cudaFuncAttributeMaxDynamicSharedMemorySize, SMEM_BYTES);

    dim3 grid(NN / NT, BATCH);   // 32 x 16 = 512 CTAs -> single wave @ 4 CTA/SM
    dim3 block(256);

    // V0 = U3
    horner_kernel<<<grid, block, SMEM_BYTES>>>(adj, x, W1, W2, b1, b2, out, 0, 3, 0, 0);
    // V1 = V0*A + U2
    horner_kernel<<<grid, block, SMEM_BYTES>>>(adj, x, W1, W2, b1, b2, out, NN / KB, 2, 0, 1);
    // V0 = V1*A + U1
    horner_kernel<<<grid, block, SMEM_BYTES>>>(adj, x, W1, W2, b1, b2, out, NN / KB, 1, 1, 0);
    // out = V0*A + U0 + bias, relu upper half
    horner_kernel<<<grid, block, SMEM_BYTES>>>(adj, x, W1, W2, b1, b2, out, NN / KB, 0, 0, 2);
}